// round 7
// baseline (speedup 1.0000x reference)
#include <cuda_runtime.h>
#include <math.h>
#include <stdint.h>

#define HIDDEN 2048
#define HEADS 16
#define HEAD_DIM 128
#define BATCH 2
#define SEQ 2048
#define MTOT (BATCH * SEQ)     // 4096
#define BH (BATCH * HEADS)     // 32
#define NELEM (MTOT * HIDDEN)  // 8M
#define WELEM (HIDDEN * HIDDEN)

// ---------------- scratch (device globals; no allocations allowed) ----------
__device__ float g_q[NELEM];
__device__ float g_k[NELEM];
__device__ float g_v[NELEM];
__device__ float g_ctx[NELEM];
__device__ float g_sc[(size_t)BH * SEQ * SEQ];   // 512 MiB

// pre-split hi/lo buffers
__device__ float g_xh[NELEM],  g_xl[NELEM];
__device__ float g_wh[4][WELEM], g_wl[4][WELEM];   // q,k,v,o
__device__ float g_qh[NELEM],  g_ql[NELEM];
__device__ float g_kh[NELEM],  g_kl[NELEM];
__device__ float g_vh[NELEM],  g_vl[NELEM];
__device__ float g_ch[NELEM],  g_cl[NELEM];

// ---------------------------------------------------------------------------
__device__ __forceinline__ uint32_t f2tf32(float x) {
    uint32_t r;
    asm("cvt.rna.tf32.f32 %0, %1;" : "=r"(r) : "f"(x));
    return r;
}

__device__ __forceinline__ void mma_tf32(float* c, const uint32_t* a, const uint32_t* b) {
    asm("mma.sync.aligned.m16n8k8.row.col.f32.tf32.tf32.f32 "
        "{%0,%1,%2,%3}, {%4,%5,%6,%7}, {%8,%9}, {%0,%1,%2,%3};"
        : "+f"(c[0]), "+f"(c[1]), "+f"(c[2]), "+f"(c[3])
        : "r"(a[0]), "r"(a[1]), "r"(a[2]), "r"(a[3]), "r"(b[0]), "r"(b[1]));
}

__device__ __forceinline__ void split_store(float v, float* hi, float* lo, int off) {
    uint32_t h = f2tf32(v);
    hi[off] = __uint_as_float(h);
    lo[off] = __uint_as_float(f2tf32(v - __uint_as_float(h)));
}

// elementwise pre-split: in -> (hi, lo), vectorized
__global__ void split_kernel(const float* __restrict__ in,
                             float* __restrict__ hi, float* __restrict__ lo, int n4) {
    int i = blockIdx.x * blockDim.x + threadIdx.x;
    if (i >= n4) return;
    float4 v = ((const float4*)in)[i];
    float4 h4, l4;
    uint32_t h;
    h = f2tf32(v.x); h4.x = __uint_as_float(h); l4.x = __uint_as_float(f2tf32(v.x - h4.x));
    h = f2tf32(v.y); h4.y = __uint_as_float(h); l4.y = __uint_as_float(f2tf32(v.y - h4.y));
    h = f2tf32(v.z); h4.z = __uint_as_float(h); l4.z = __uint_as_float(f2tf32(v.z - h4.z));
    h = f2tf32(v.w); h4.w = __uint_as_float(h); l4.w = __uint_as_float(f2tf32(v.w - h4.w));
    ((float4*)hi)[i] = h4;
    ((float4*)lo)[i] = l4;
}

#define KC 32
#define SROW 36
#define SM_TILE (128 * SROW)
#define GEMM_SMEM (4 * SM_TILE * 4)

// one KC-chunk of 3xTF32 mma on staged hi/lo tiles (proven core, unchanged)
__device__ __forceinline__ void mma_chunk(
    const float* Ah, const float* Al, const float* Bh, const float* Bl,
    int wm, int wn, int gid, int tq, float acc[4][4][4]) {
#pragma unroll
    for (int ks = 0; ks < 4; ks++) {
        const int kb = ks * 8;
        uint32_t bh[4][2], bl[4][2];
#pragma unroll
        for (int nt = 0; nt < 4; nt++) {
            int nr = (wn + nt * 8 + gid) * SROW + kb + tq;
            bh[nt][0] = __float_as_uint(Bh[nr]);
            bh[nt][1] = __float_as_uint(Bh[nr + 4]);
            bl[nt][0] = __float_as_uint(Bl[nr]);
            bl[nt][1] = __float_as_uint(Bl[nr + 4]);
        }
        uint32_t af[4][4];
#pragma unroll
        for (int mt = 0; mt < 4; mt++) {
            int r = (wm + mt * 16 + gid) * SROW + kb + tq;
            af[mt][0] = __float_as_uint(Ah[r]);
            af[mt][1] = __float_as_uint(Ah[r + 8 * SROW]);
            af[mt][2] = __float_as_uint(Ah[r + 4]);
            af[mt][3] = __float_as_uint(Ah[r + 8 * SROW + 4]);
        }
#pragma unroll
        for (int mt = 0; mt < 4; mt++)
#pragma unroll
            for (int nt = 0; nt < 4; nt++) {
                mma_tf32(acc[mt][nt], af[mt], bh[nt]);   // hi*hi
                mma_tf32(acc[mt][nt], af[mt], bl[nt]);   // hi*lo
            }
#pragma unroll
        for (int mt = 0; mt < 4; mt++) {
            int r = (wm + mt * 16 + gid) * SROW + kb + tq;
            af[mt][0] = __float_as_uint(Al[r]);
            af[mt][1] = __float_as_uint(Al[r + 8 * SROW]);
            af[mt][2] = __float_as_uint(Al[r + 4]);
            af[mt][3] = __float_as_uint(Al[r + 8 * SROW + 4]);
        }
#pragma unroll
        for (int mt = 0; mt < 4; mt++)
#pragma unroll
            for (int nt = 0; nt < 4; nt++)
                mma_tf32(acc[mt][nt], af[mt], bh[nt]);   // lo*hi
    }
}

// ---------------------------------------------------------------------------
// Pre-split NT GEMM: C = A * B^T from hi/lo operand pairs. Pure-copy staging.
// ldab = row stride of A/B hi-lo arrays (HIDDEN everywhere here).
// ---------------------------------------------------------------------------
__global__ __launch_bounds__(256, 2)
void gemm_pre(const float* __restrict__ Ahg, const float* __restrict__ Alg,
              const float* __restrict__ Bhg, const float* __restrict__ Blg,
              float* __restrict__ C) {
    extern __shared__ __align__(16) float sm[];
    float* Ah = sm;
    float* Al = Ah + SM_TILE;
    float* Bh = Al + SM_TILE;
    float* Bl = Bh + SM_TILE;

    const int tid = threadIdx.x;
    const int warp = tid >> 5, lane = tid & 31;
    const int gid = lane >> 2, tq = lane & 3;
    const int wm = (warp & 1) * 64;
    const int wn = (warp >> 1) * 32;
    const int m0 = blockIdx.y * 128, n0 = blockIdx.x * 128;
    const int lr = tid >> 1;
    const int lc = (tid & 1) * 16;

    float acc[4][4][4];
#pragma unroll
    for (int mt = 0; mt < 4; mt++)
#pragma unroll
        for (int nt = 0; nt < 4; nt++)
#pragma unroll
            for (int r = 0; r < 4; r++) acc[mt][nt][r] = 0.f;

    const size_t arow = (size_t)(m0 + lr) * HIDDEN + lc;
    const size_t brow = (size_t)(n0 + lr) * HIDDEN + lc;

    for (int kt = 0; kt < HIDDEN; kt += KC) {
        float4 ah[4], al[4], bh[4], bl[4];
#pragma unroll
        for (int i = 0; i < 4; i++) {
            ah[i] = *(const float4*)(Ahg + arow + kt + 4 * i);
            al[i] = *(const float4*)(Alg + arow + kt + 4 * i);
            bh[i] = *(const float4*)(Bhg + brow + kt + 4 * i);
            bl[i] = *(const float4*)(Blg + brow + kt + 4 * i);
        }
        __syncthreads();
        const int off = lr * SROW + lc;
#pragma unroll
        for (int i = 0; i < 4; i++) {
            *(float4*)&Ah[off + 4 * i] = ah[i];
            *(float4*)&Al[off + 4 * i] = al[i];
            *(float4*)&Bh[off + 4 * i] = bh[i];
            *(float4*)&Bl[off + 4 * i] = bl[i];
        }
        __syncthreads();
        mma_chunk(Ah, Al, Bh, Bl, wm, wn, gid, tq, acc);
    }

#pragma unroll
    for (int mt = 0; mt < 4; mt++) {
        int row = m0 + wm + mt * 16 + gid;
#pragma unroll
        for (int nt = 0; nt < 4; nt++) {
            int col = n0 + wn + nt * 8 + 2 * tq;
            *(float2*)&C[(size_t)row * HIDDEN + col] =
                make_float2(acc[mt][nt][0], acc[mt][nt][1]);
            *(float2*)&C[(size_t)(row + 8) * HIDDEN + col] =
                make_float2(acc[mt][nt][2], acc[mt][nt][3]);
        }
    }
}

// ---------------------------------------------------------------------------
// Scores from pre-split q/k: S = (Q.K^T)*scale, 128x128 lower-triangle blocks.
// ---------------------------------------------------------------------------
__global__ __launch_bounds__(256, 2)
void scores_pre() {
    const int k0 = blockIdx.x * 128;
    const int q0 = blockIdx.y * 128;
    if (k0 > q0) return;
    const int bh = blockIdx.z;
    const int b = bh >> 4, h = bh & 15;

    extern __shared__ __align__(16) float sm[];
    float* Ah = sm;
    float* Al = Ah + SM_TILE;
    float* Bh = Al + SM_TILE;
    float* Bl = Bh + SM_TILE;

    const int tid = threadIdx.x;
    const int warp = tid >> 5, lane = tid & 31;
    const int gid = lane >> 2, tq = lane & 3;
    const int wm = (warp & 1) * 64;
    const int wn = (warp >> 1) * 32;
    const int lr = tid >> 1;
    const int lc = (tid & 1) * 16;

    const size_t hb = (size_t)b * SEQ * HIDDEN + h * HEAD_DIM;
    float* S = g_sc + (size_t)bh * SEQ * SEQ;

    float acc[4][4][4];
#pragma unroll
    for (int mt = 0; mt < 4; mt++)
#pragma unroll
        for (int nt = 0; nt < 4; nt++)
#pragma unroll
            for (int r = 0; r < 4; r++) acc[mt][nt][r] = 0.f;

    const size_t qrow = hb + (size_t)(q0 + lr) * HIDDEN + lc;
    const size_t krow = hb + (size_t)(k0 + lr) * HIDDEN + lc;

#pragma unroll
    for (int kt = 0; kt < HEAD_DIM; kt += KC) {
        float4 ah[4], al[4], bh[4], bl[4];
#pragma unroll
        for (int i = 0; i < 4; i++) {
            ah[i] = *(const float4*)(g_qh + qrow + kt + 4 * i);
            al[i] = *(const float4*)(g_ql + qrow + kt + 4 * i);
            bh[i] = *(const float4*)(g_kh + krow + kt + 4 * i);
            bl[i] = *(const float4*)(g_kl + krow + kt + 4 * i);
        }
        __syncthreads();
        const int off = lr * SROW + lc;
#pragma unroll
        for (int i = 0; i < 4; i++) {
            *(float4*)&Ah[off + 4 * i] = ah[i];
            *(float4*)&Al[off + 4 * i] = al[i];
            *(float4*)&Bh[off + 4 * i] = bh[i];
            *(float4*)&Bl[off + 4 * i] = bl[i];
        }
        __syncthreads();
        mma_chunk(Ah, Al, Bh, Bl, wm, wn, gid, tq, acc);
    }

    const float scale = 0.08838834764831845f;
#pragma unroll
    for (int mt = 0; mt < 4; mt++) {
        int row = q0 + wm + mt * 16 + gid;
#pragma unroll
        for (int nt = 0; nt < 4; nt++) {
            int col = k0 + wn + nt * 8 + 2 * tq;
            *(float2*)&S[(size_t)row * SEQ + col] =
                make_float2(acc[mt][nt][0] * scale, acc[mt][nt][1] * scale);
            *(float2*)&S[(size_t)(row + 8) * SEQ + col] =
                make_float2(acc[mt][nt][2] * scale, acc[mt][nt][3] * scale);
        }
    }
}

// ---------------------------------------------------------------------------
// PV: ctx = P * V. P split in-kernel (used once); V pre-split, staged transposed.
// ---------------------------------------------------------------------------
__global__ __launch_bounds__(256, 2)
void pv_pre() {
    const int q0 = blockIdx.x * 128;
    const int bh = blockIdx.y;
    const int b = bh >> 4, h = bh & 15;

    extern __shared__ __align__(16) float sm[];
    float* Ah = sm;
    float* Al = Ah + SM_TILE;
    float* Bh = Al + SM_TILE;
    float* Bl = Bh + SM_TILE;

    const int tid = threadIdx.x;
    const int warp = tid >> 5, lane = tid & 31;
    const int gid = lane >> 2, tq = lane & 3;
    const int wm = (warp & 1) * 64;
    const int wn = (warp >> 1) * 32;
    const int lr = tid >> 1;
    const int lc = (tid & 1) * 16;
    const int vr = tid >> 3;            // 0..31
    const int vd = (tid & 7) * 16;      // 0..112

    const float* P = g_sc + (size_t)bh * SEQ * SEQ;
    const size_t hb = (size_t)b * SEQ * HIDDEN + h * HEAD_DIM;
    float* O = g_ctx + hb;

    float acc[4][4][4];
#pragma unroll
    for (int mt = 0; mt < 4; mt++)
#pragma unroll
        for (int nt = 0; nt < 4; nt++)
#pragma unroll
            for (int r = 0; r < 4; r++) acc[mt][nt][r] = 0.f;

    const int kmax = q0 + 128;
    for (int kt = 0; kt < kmax; kt += KC) {
        float4 pv4[4], vh[4], vl[4];
#pragma unroll
        for (int i = 0; i < 4; i++) {
            pv4[i] = *(const float4*)&P[(size_t)(q0 + lr) * SEQ + kt + lc + 4 * i];
            vh[i]  = *(const float4*)&g_vh[hb + (size_t)(kt + vr) * HIDDEN + vd + 4 * i];
            vl[i]  = *(const float4*)&g_vl[hb + (size_t)(kt + vr) * HIDDEN + vd + 4 * i];
        }
        __syncthreads();
#pragma unroll
        for (int i = 0; i < 4; i++) {
            int off = lr * SROW + lc + 4 * i;
            split_store(pv4[i].x, Ah, Al, off + 0);
            split_store(pv4[i].y, Ah, Al, off + 1);
            split_store(pv4[i].z, Ah, Al, off + 2);
            split_store(pv4[i].w, Ah, Al, off + 3);
            // V transposed copy: Bs[d][k]
            Bh[(vd + 4 * i + 0) * SROW + vr] = vh[i].x;
            Bh[(vd + 4 * i + 1) * SROW + vr] = vh[i].y;
            Bh[(vd + 4 * i + 2) * SROW + vr] = vh[i].z;
            Bh[(vd + 4 * i + 3) * SROW + vr] = vh[i].w;
            Bl[(vd + 4 * i + 0) * SROW + vr] = vl[i].x;
            Bl[(vd + 4 * i + 1) * SROW + vr] = vl[i].y;
            Bl[(vd + 4 * i + 2) * SROW + vr] = vl[i].z;
            Bl[(vd + 4 * i + 3) * SROW + vr] = vl[i].w;
        }
        __syncthreads();
        mma_chunk(Ah, Al, Bh, Bl, wm, wn, gid, tq, acc);
    }

#pragma unroll
    for (int mt = 0; mt < 4; mt++) {
        int row = q0 + wm + mt * 16 + gid;
#pragma unroll
        for (int nt = 0; nt < 4; nt++) {
            int col = wn + nt * 8 + 2 * tq;
            *(float2*)&O[(size_t)row * HIDDEN + col] =
                make_float2(acc[mt][nt][0], acc[mt][nt][1]);
            *(float2*)&O[(size_t)(row + 8) * HIDDEN + col] =
                make_float2(acc[mt][nt][2], acc[mt][nt][3]);
        }
    }
}

// ---------------------------------------------------------------------------
// RoPE (unchanged, proven).
// ---------------------------------------------------------------------------
__global__ void rope2() {
    int idx = blockIdx.x * blockDim.x + threadIdx.x;
    if (idx >= MTOT * 1024) return;
    int d = idx & 63;
    int h = (idx >> 6) & 15;
    int row = idx >> 10;
    int s = row & (SEQ - 1);

    double inv = pow(10000.0, -((double)d) / 64.0);
    double ang = (double)s * inv;
    float c = (float)cos(ang);
    float sn = (float)sin(ang);

    size_t i1 = (size_t)row * HIDDEN + h * HEAD_DIM + d;
    float q1 = g_q[i1], q2 = g_q[i1 + 64];
    g_q[i1]      = q1 * c - q2 * sn;
    g_q[i1 + 64] = q2 * c + q1 * sn;
    float k1 = g_k[i1], k2 = g_k[i1 + 64];
    g_k[i1]      = k1 * c - k2 * sn;
    g_k[i1 + 64] = k2 * c + k1 * sn;
}

// ---------------------------------------------------------------------------
// Softmax (unchanged, proven).
// ---------------------------------------------------------------------------
__global__ __launch_bounds__(256)
void softmax_rows() {
    const int row = blockIdx.x;
    const int q = row & (SEQ - 1);
    const int bh = row >> 11;
    float* P = g_sc + (size_t)bh * SEQ * SEQ + (size_t)q * SEQ;
    const int n = q + 1;
    const int tid = threadIdx.x;
    __shared__ float red[256];

    float mx = -1e30f;
    for (int j = tid; j < n; j += 256) mx = fmaxf(mx, P[j]);
    red[tid] = mx;
    __syncthreads();
    for (int s = 128; s > 0; s >>= 1) {
        if (tid < s) red[tid] = fmaxf(red[tid], red[tid + s]);
        __syncthreads();
    }
    float m = red[0];
    __syncthreads();

    float sum = 0.f;
    for (int j = tid; j < n; j += 256) sum += __expf(P[j] - m);
    red[tid] = sum;
    __syncthreads();
    for (int s = 128; s > 0; s >>= 1) {
        if (tid < s) red[tid] += red[tid + s];
        __syncthreads();
    }
    float inv = 1.0f / red[0];

    for (int j = tid; j < n; j += 256) P[j] = __expf(P[j] - m) * inv;
    for (int j = n + tid; j < SEQ; j += 256) P[j] = 0.f;
}

// ---------------------------------------------------------------------------
extern "C" void kernel_launch(void* const* d_in, const int* in_sizes, int n_in,
                              void* d_out, int out_size) {
    int xi = 0;
    for (int i = 0; i < n_in; i++)
        if (in_sizes[i] == NELEM) { xi = i; break; }

    const float* x;
    const float *Wq, *Wk, *Wv, *Wo;
    if (xi == 0) {
        x  = (const float*)d_in[0];
        Wq = (const float*)d_in[1];
        Wk = (const float*)d_in[2];
        Wv = (const float*)d_in[3];
        Wo = (const float*)d_in[4];
    } else {
        const float* w[4]; int j = 0;
        for (int i = 0; i < n_in; i++)
            if (i != xi) w[j++] = (const float*)d_in[i];
        x = (const float*)d_in[xi];
        Wk = w[0]; Wo = w[1]; Wq = w[2]; Wv = w[3];
    }

    float *qp, *kp, *vp, *cp;
    float *xh, *xl, *wh, *wl, *qh, *ql, *kh, *kl, *vh, *vl, *ch, *cl;
    cudaGetSymbolAddress((void**)&qp, g_q);
    cudaGetSymbolAddress((void**)&kp, g_k);
    cudaGetSymbolAddress((void**)&vp, g_v);
    cudaGetSymbolAddress((void**)&cp, g_ctx);
    cudaGetSymbolAddress((void**)&xh, g_xh);
    cudaGetSymbolAddress((void**)&xl, g_xl);
    cudaGetSymbolAddress((void**)&wh, g_wh);
    cudaGetSymbolAddress((void**)&wl, g_wl);
    cudaGetSymbolAddress((void**)&qh, g_qh);
    cudaGetSymbolAddress((void**)&ql, g_ql);
    cudaGetSymbolAddress((void**)&kh, g_kh);
    cudaGetSymbolAddress((void**)&kl, g_kl);
    cudaGetSymbolAddress((void**)&vh, g_vh);
    cudaGetSymbolAddress((void**)&vl, g_vl);
    cudaGetSymbolAddress((void**)&ch, g_ch);
    cudaGetSymbolAddress((void**)&cl, g_cl);

    cudaFuncSetAttribute(gemm_pre,
                         cudaFuncAttributeMaxDynamicSharedMemorySize, GEMM_SMEM);
    cudaFuncSetAttribute(scores_pre,
                         cudaFuncAttributeMaxDynamicSharedMemorySize, GEMM_SMEM);
    cudaFuncSetAttribute(pv_pre,
                         cudaFuncAttributeMaxDynamicSharedMemorySize, GEMM_SMEM);

    const int SB = 256;
    // pre-split inputs
    split_kernel<<<NELEM / 4 / SB, SB>>>(x, xh, xl, NELEM / 4);
    split_kernel<<<WELEM / 4 / SB, SB>>>(Wq, wh + 0 * WELEM, wl + 0 * WELEM, WELEM / 4);
    split_kernel<<<WELEM / 4 / SB, SB>>>(Wk, wh + 1 * WELEM, wl + 1 * WELEM, WELEM / 4);
    split_kernel<<<WELEM / 4 / SB, SB>>>(Wv, wh + 2 * WELEM, wl + 2 * WELEM, WELEM / 4);
    split_kernel<<<WELEM / 4 / SB, SB>>>(Wo, wh + 3 * WELEM, wl + 3 * WELEM, WELEM / 4);

    dim3 gg(HIDDEN / 128, MTOT / 128);   // (16, 32)
    gemm_pre<<<gg, 256, GEMM_SMEM>>>(xh, xl, wh + 0 * WELEM, wl + 0 * WELEM, qp);
    gemm_pre<<<gg, 256, GEMM_SMEM>>>(xh, xl, wh + 1 * WELEM, wl + 1 * WELEM, kp);
    gemm_pre<<<gg, 256, GEMM_SMEM>>>(xh, xl, wh + 2 * WELEM, wl + 2 * WELEM, vp);

    rope2<<<(MTOT * 1024 + 255) / 256, 256>>>();

    // split roped q/k and v
    split_kernel<<<NELEM / 4 / SB, SB>>>(qp, qh, ql, NELEM / 4);
    split_kernel<<<NELEM / 4 / SB, SB>>>(kp, kh, kl, NELEM / 4);
    split_kernel<<<NELEM / 4 / SB, SB>>>(vp, vh, vl, NELEM / 4);

    scores_pre<<<dim3(SEQ / 128, SEQ / 128, BH), 256, GEMM_SMEM>>>();
    softmax_rows<<<BH * SEQ, 256>>>();
    pv_pre<<<dim3(SEQ / 128, BH), 256, GEMM_SMEM>>>();

    split_kernel<<<NELEM / 4 / SB, SB>>>(cp, ch, cl, NELEM / 4);
    gemm_pre<<<gg, 256, GEMM_SMEM>>>(ch, cl, wh + 3 * WELEM, wl + 3 * WELEM, (float*)d_out);
}

// round 9
// speedup vs baseline: 1.1803x; 1.1803x over previous
#include <cuda_runtime.h>
#include <math.h>
#include <stdint.h>

#define HIDDEN 2048
#define HEADS 16
#define HEAD_DIM 128
#define BATCH 2
#define SEQ 2048
#define MTOT (BATCH * SEQ)     // 4096
#define BH (BATCH * HEADS)     // 32

// ---------------- scratch (device globals; no allocations allowed) ----------
__device__ float g_q[MTOT * HIDDEN];
__device__ float g_k[MTOT * HIDDEN];
__device__ float g_v[MTOT * HIDDEN];
__device__ float g_ctx[MTOT * HIDDEN];
__device__ float g_sc[(size_t)BH * SEQ * SEQ];   // 512 MiB score/prob matrix

// ---------------------------------------------------------------------------
__device__ __forceinline__ uint32_t f2tf32(float x) {
    uint32_t r;
    asm("cvt.rna.tf32.f32 %0, %1;" : "=r"(r) : "f"(x));
    return r;
}

__device__ __forceinline__ void mma_tf32(float* c, const uint32_t* a, const uint32_t* b) {
    asm("mma.sync.aligned.m16n8k8.row.col.f32.tf32.tf32.f32 "
        "{%0,%1,%2,%3}, {%4,%5,%6,%7}, {%8,%9}, {%0,%1,%2,%3};"
        : "+f"(c[0]), "+f"(c[1]), "+f"(c[2]), "+f"(c[3])
        : "r"(a[0]), "r"(a[1]), "r"(a[2]), "r"(a[3]), "r"(b[0]), "r"(b[1]));
}

__device__ __forceinline__ void split_store(float v, float* hi, float* lo, int off) {
    uint32_t h = f2tf32(v);
    hi[off] = __uint_as_float(h);
    lo[off] = __uint_as_float(f2tf32(v - __uint_as_float(h)));
}

#define KC 32
#define SROW 36
#define SM_TILE (128 * SROW)
#define GEMM_SMEM (4 * SM_TILE * 4)   // bytes: Ah, Al, Bh, Bl

// one KC-chunk of 3xTF32 mma on staged hi/lo tiles (proven core, unchanged)
__device__ __forceinline__ void mma_chunk(
    const float* Ah, const float* Al, const float* Bh, const float* Bl,
    int wm, int wn, int gid, int tq, float acc[4][4][4]) {
#pragma unroll
    for (int ks = 0; ks < 4; ks++) {
        const int kb = ks * 8;
        uint32_t bh[4][2], bl[4][2];
#pragma unroll
        for (int nt = 0; nt < 4; nt++) {
            int nr = (wn + nt * 8 + gid) * SROW + kb + tq;
            bh[nt][0] = __float_as_uint(Bh[nr]);
            bh[nt][1] = __float_as_uint(Bh[nr + 4]);
            bl[nt][0] = __float_as_uint(Bl[nr]);
            bl[nt][1] = __float_as_uint(Bl[nr + 4]);
        }
        uint32_t af[4][4];
#pragma unroll
        for (int mt = 0; mt < 4; mt++) {
            int r = (wm + mt * 16 + gid) * SROW + kb + tq;
            af[mt][0] = __float_as_uint(Ah[r]);
            af[mt][1] = __float_as_uint(Ah[r + 8 * SROW]);
            af[mt][2] = __float_as_uint(Ah[r + 4]);
            af[mt][3] = __float_as_uint(Ah[r + 8 * SROW + 4]);
        }
#pragma unroll
        for (int mt = 0; mt < 4; mt++)
#pragma unroll
            for (int nt = 0; nt < 4; nt++) {
                mma_tf32(acc[mt][nt], af[mt], bh[nt]);   // hi*hi
                mma_tf32(acc[mt][nt], af[mt], bl[nt]);   // hi*lo
            }
#pragma unroll
        for (int mt = 0; mt < 4; mt++) {
            int r = (wm + mt * 16 + gid) * SROW + kb + tq;
            af[mt][0] = __float_as_uint(Al[r]);
            af[mt][1] = __float_as_uint(Al[r + 8 * SROW]);
            af[mt][2] = __float_as_uint(Al[r + 4]);
            af[mt][3] = __float_as_uint(Al[r + 8 * SROW + 4]);
        }
#pragma unroll
        for (int mt = 0; mt < 4; mt++)
#pragma unroll
            for (int nt = 0; nt < 4; nt++)
                mma_tf32(acc[mt][nt], af[mt], bh[nt]);   // lo*hi
    }
}

// ---------------------------------------------------------------------------
// Split-tf32 NT GEMM, software-pipelined: prefetch chunk k+1 into registers
// while tensor cores chew on chunk k.
// C[M,N] = A[M,K] * W[N,K]^T ; M=4096, N=K=2048.
// ---------------------------------------------------------------------------
__global__ __launch_bounds__(256)
void gemm_tf32(const float* __restrict__ A, const float* __restrict__ W,
               float* __restrict__ C) {
    extern __shared__ __align__(16) float sm[];
    float* Ah = sm;
    float* Al = Ah + SM_TILE;
    float* Bh = Al + SM_TILE;
    float* Bl = Bh + SM_TILE;

    const int tid = threadIdx.x;
    const int warp = tid >> 5, lane = tid & 31;
    const int gid = lane >> 2, tq = lane & 3;
    const int wm = (warp & 1) * 64;
    const int wn = (warp >> 1) * 32;
    const int m0 = blockIdx.y * 128, n0 = blockIdx.x * 128;
    const int lr = tid >> 1;
    const int lc = (tid & 1) * 16;

    float acc[4][4][4];
#pragma unroll
    for (int mt = 0; mt < 4; mt++)
#pragma unroll
        for (int nt = 0; nt < 4; nt++)
#pragma unroll
            for (int r = 0; r < 4; r++) acc[mt][nt][r] = 0.f;

    const float* Ap = A + (size_t)(m0 + lr) * HIDDEN + lc;
    const float* Wp = W + (size_t)(n0 + lr) * HIDDEN + lc;

    float4 av[4], wv[4];
#pragma unroll
    for (int i = 0; i < 4; i++) {        // preload chunk 0
        av[i] = *(const float4*)(Ap + 4 * i);
        wv[i] = *(const float4*)(Wp + 4 * i);
    }

    for (int kt = 0; kt < HIDDEN; kt += KC) {
        __syncthreads();
#pragma unroll
        for (int i = 0; i < 4; i++) {
            int off = lr * SROW + lc + 4 * i;
            split_store(av[i].x, Ah, Al, off + 0);
            split_store(av[i].y, Ah, Al, off + 1);
            split_store(av[i].z, Ah, Al, off + 2);
            split_store(av[i].w, Ah, Al, off + 3);
            split_store(wv[i].x, Bh, Bl, off + 0);
            split_store(wv[i].y, Bh, Bl, off + 1);
            split_store(wv[i].z, Bh, Bl, off + 2);
            split_store(wv[i].w, Bh, Bl, off + 3);
        }
        __syncthreads();
        if (kt + KC < HIDDEN) {          // prefetch next chunk (hidden by mma)
#pragma unroll
            for (int i = 0; i < 4; i++) {
                av[i] = *(const float4*)(Ap + kt + KC + 4 * i);
                wv[i] = *(const float4*)(Wp + kt + KC + 4 * i);
            }
        }
        mma_chunk(Ah, Al, Bh, Bl, wm, wn, gid, tq, acc);
    }

#pragma unroll
    for (int mt = 0; mt < 4; mt++) {
        int row = m0 + wm + mt * 16 + gid;
#pragma unroll
        for (int nt = 0; nt < 4; nt++) {
            int col = n0 + wn + nt * 8 + 2 * tq;
            *(float2*)&C[(size_t)row * HIDDEN + col] =
                make_float2(acc[mt][nt][0], acc[mt][nt][1]);
            *(float2*)&C[(size_t)(row + 8) * HIDDEN + col] =
                make_float2(acc[mt][nt][2], acc[mt][nt][3]);
        }
    }
}

// ---------------------------------------------------------------------------
// Scores, pipelined: S = (Q.K^T)*scale, 128x128 lower-triangle blocks.
// ---------------------------------------------------------------------------
__global__ __launch_bounds__(256)
void scores_tf32() {
    const int k0 = blockIdx.x * 128;
    const int q0 = blockIdx.y * 128;
    if (k0 > q0) return;
    const int bh = blockIdx.z;
    const int b = bh >> 4, h = bh & 15;

    extern __shared__ __align__(16) float sm[];
    float* Ah = sm;
    float* Al = Ah + SM_TILE;
    float* Bh = Al + SM_TILE;
    float* Bl = Bh + SM_TILE;

    const int tid = threadIdx.x;
    const int warp = tid >> 5, lane = tid & 31;
    const int gid = lane >> 2, tq = lane & 3;
    const int wm = (warp & 1) * 64;
    const int wn = (warp >> 1) * 32;
    const int lr = tid >> 1;
    const int lc = (tid & 1) * 16;

    const float* Q = g_q + (size_t)b * SEQ * HIDDEN + h * HEAD_DIM;
    const float* K = g_k + (size_t)b * SEQ * HIDDEN + h * HEAD_DIM;
    float* S = g_sc + (size_t)bh * SEQ * SEQ;

    float acc[4][4][4];
#pragma unroll
    for (int mt = 0; mt < 4; mt++)
#pragma unroll
        for (int nt = 0; nt < 4; nt++)
#pragma unroll
            for (int r = 0; r < 4; r++) acc[mt][nt][r] = 0.f;

    const float* Qp = Q + (size_t)(q0 + lr) * HIDDEN + lc;
    const float* Kp = K + (size_t)(k0 + lr) * HIDDEN + lc;

    float4 av[4], wv[4];
#pragma unroll
    for (int i = 0; i < 4; i++) {
        av[i] = *(const float4*)(Qp + 4 * i);
        wv[i] = *(const float4*)(Kp + 4 * i);
    }

#pragma unroll
    for (int kt = 0; kt < HEAD_DIM; kt += KC) {
        __syncthreads();
#pragma unroll
        for (int i = 0; i < 4; i++) {
            int off = lr * SROW + lc + 4 * i;
            split_store(av[i].x, Ah, Al, off + 0);
            split_store(av[i].y, Ah, Al, off + 1);
            split_store(av[i].z, Ah, Al, off + 2);
            split_store(av[i].w, Ah, Al, off + 3);
            split_store(wv[i].x, Bh, Bl, off + 0);
            split_store(wv[i].y, Bh, Bl, off + 1);
            split_store(wv[i].z, Bh, Bl, off + 2);
            split_store(wv[i].w, Bh, Bl, off + 3);
        }
        __syncthreads();
        if (kt + KC < HEAD_DIM) {
#pragma unroll
            for (int i = 0; i < 4; i++) {
                av[i] = *(const float4*)(Qp + kt + KC + 4 * i);
                wv[i] = *(const float4*)(Kp + kt + KC + 4 * i);
            }
        }
        mma_chunk(Ah, Al, Bh, Bl, wm, wn, gid, tq, acc);
    }

    const float scale = 0.08838834764831845f;  // 1/sqrt(128)
#pragma unroll
    for (int mt = 0; mt < 4; mt++) {
        int row = q0 + wm + mt * 16 + gid;
#pragma unroll
        for (int nt = 0; nt < 4; nt++) {
            int col = k0 + wn + nt * 8 + 2 * tq;
            *(float2*)&S[(size_t)row * SEQ + col] =
                make_float2(acc[mt][nt][0] * scale, acc[mt][nt][1] * scale);
            *(float2*)&S[(size_t)(row + 8) * SEQ + col] =
                make_float2(acc[mt][nt][2] * scale, acc[mt][nt][3] * scale);
        }
    }
}

// ---------------------------------------------------------------------------
// PV, pipelined: ctx = P * V; V staged transposed (Bs[d][k]).
// k-loop bounded at q0+128; P is zero beyond each row's diagonal.
// ---------------------------------------------------------------------------
__global__ __launch_bounds__(256)
void pv_tf32() {
    const int q0 = blockIdx.x * 128;
    const int bh = blockIdx.y;
    const int b = bh >> 4, h = bh & 15;

    extern __shared__ __align__(16) float sm[];
    float* Ah = sm;
    float* Al = Ah + SM_TILE;
    float* Bh = Al + SM_TILE;
    float* Bl = Bh + SM_TILE;

    const int tid = threadIdx.x;
    const int warp = tid >> 5, lane = tid & 31;
    const int gid = lane >> 2, tq = lane & 3;
    const int wm = (warp & 1) * 64;
    const int wn = (warp >> 1) * 32;
    const int lr = tid >> 1;
    const int lc = (tid & 1) * 16;
    const int vr = tid >> 3;            // 0..31 (k row within chunk)
    const int vd = (tid & 7) * 16;      // d base: 0..112

    const float* P = g_sc + (size_t)bh * SEQ * SEQ;
    const float* V = g_v + (size_t)b * SEQ * HIDDEN + h * HEAD_DIM;
    float* O = g_ctx + (size_t)b * SEQ * HIDDEN + h * HEAD_DIM;

    float acc[4][4][4];
#pragma unroll
    for (int mt = 0; mt < 4; mt++)
#pragma unroll
        for (int nt = 0; nt < 4; nt++)
#pragma unroll
            for (int r = 0; r < 4; r++) acc[mt][nt][r] = 0.f;

    const int kmax = q0 + 128;

    float4 pv4[4], vv[4];
#pragma unroll
    for (int i = 0; i < 4; i++) {
        pv4[i] = *(const float4*)&P[(size_t)(q0 + lr) * SEQ + lc + 4 * i];
        vv[i]  = *(const float4*)&V[(size_t)vr * HIDDEN + vd + 4 * i];
    }

    for (int kt = 0; kt < kmax; kt += KC) {
        __syncthreads();
#pragma unroll
        for (int i = 0; i < 4; i++) {
            int off = lr * SROW + lc + 4 * i;
            split_store(pv4[i].x, Ah, Al, off + 0);
            split_store(pv4[i].y, Ah, Al, off + 1);
            split_store(pv4[i].z, Ah, Al, off + 2);
            split_store(pv4[i].w, Ah, Al, off + 3);
            // V transposed: Bs[d][k]
            split_store(vv[i].x, Bh, Bl, (vd + 4 * i + 0) * SROW + vr);
            split_store(vv[i].y, Bh, Bl, (vd + 4 * i + 1) * SROW + vr);
            split_store(vv[i].z, Bh, Bl, (vd + 4 * i + 2) * SROW + vr);
            split_store(vv[i].w, Bh, Bl, (vd + 4 * i + 3) * SROW + vr);
        }
        __syncthreads();
        if (kt + KC < kmax) {
#pragma unroll
            for (int i = 0; i < 4; i++) {
                pv4[i] = *(const float4*)&P[(size_t)(q0 + lr) * SEQ + kt + KC + lc + 4 * i];
                vv[i]  = *(const float4*)&V[(size_t)(kt + KC + vr) * HIDDEN + vd + 4 * i];
            }
        }
        mma_chunk(Ah, Al, Bh, Bl, wm, wn, gid, tq, acc);
    }

#pragma unroll
    for (int mt = 0; mt < 4; mt++) {
        int row = q0 + wm + mt * 16 + gid;
#pragma unroll
        for (int nt = 0; nt < 4; nt++) {
            int col = wn + nt * 8 + 2 * tq;
            *(float2*)&O[(size_t)row * HIDDEN + col] =
                make_float2(acc[mt][nt][0], acc[mt][nt][1]);
            *(float2*)&O[(size_t)(row + 8) * HIDDEN + col] =
                make_float2(acc[mt][nt][2], acc[mt][nt][3]);
        }
    }
}

// ---------------------------------------------------------------------------
// RoPE (unchanged, proven).
// ---------------------------------------------------------------------------
__global__ void rope2() {
    int idx = blockIdx.x * blockDim.x + threadIdx.x;
    if (idx >= MTOT * 1024) return;
    int d = idx & 63;
    int h = (idx >> 6) & 15;
    int row = idx >> 10;
    int s = row & (SEQ - 1);

    double inv = pow(10000.0, -((double)d) / 64.0);
    double ang = (double)s * inv;
    float c = (float)cos(ang);
    float sn = (float)sin(ang);

    size_t i1 = (size_t)row * HIDDEN + h * HEAD_DIM + d;
    float q1 = g_q[i1], q2 = g_q[i1 + 64];
    g_q[i1]      = q1 * c - q2 * sn;
    g_q[i1 + 64] = q2 * c + q1 * sn;
    float k1 = g_k[i1], k2 = g_k[i1 + 64];
    g_k[i1]      = k1 * c - k2 * sn;
    g_k[i1 + 64] = k2 * c + k1 * sn;
}

// ---------------------------------------------------------------------------
// Softmax (unchanged, proven).
// ---------------------------------------------------------------------------
__global__ __launch_bounds__(256)
void softmax_rows() {
    const int row = blockIdx.x;
    const int q = row & (SEQ - 1);
    const int bh = row >> 11;
    float* P = g_sc + (size_t)bh * SEQ * SEQ + (size_t)q * SEQ;
    const int n = q + 1;
    const int tid = threadIdx.x;
    __shared__ float red[256];

    float mx = -1e30f;
    for (int j = tid; j < n; j += 256) mx = fmaxf(mx, P[j]);
    red[tid] = mx;
    __syncthreads();
    for (int s = 128; s > 0; s >>= 1) {
        if (tid < s) red[tid] = fmaxf(red[tid], red[tid + s]);
        __syncthreads();
    }
    float m = red[0];
    __syncthreads();

    float sum = 0.f;
    for (int j = tid; j < n; j += 256) sum += __expf(P[j] - m);
    red[tid] = sum;
    __syncthreads();
    for (int s = 128; s > 0; s >>= 1) {
        if (tid < s) red[tid] += red[tid + s];
        __syncthreads();
    }
    float inv = 1.0f / red[0];

    for (int j = tid; j < n; j += 256) P[j] = __expf(P[j] - m) * inv;
    for (int j = n + tid; j < SEQ; j += 256) P[j] = 0.f;
}

// ---------------------------------------------------------------------------
extern "C" void kernel_launch(void* const* d_in, const int* in_sizes, int n_in,
                              void* d_out, int out_size) {
    int xi = 0;
    for (int i = 0; i < n_in; i++)
        if (in_sizes[i] == MTOT * HIDDEN) { xi = i; break; }

    const float* x;
    const float *Wq, *Wk, *Wv, *Wo;
    if (xi == 0) {
        x  = (const float*)d_in[0];
        Wq = (const float*)d_in[1];
        Wk = (const float*)d_in[2];
        Wv = (const float*)d_in[3];
        Wo = (const float*)d_in[4];
    } else {
        const float* w[4]; int j = 0;
        for (int i = 0; i < n_in; i++)
            if (i != xi) w[j++] = (const float*)d_in[i];
        x = (const float*)d_in[xi];
        Wk = w[0]; Wo = w[1]; Wq = w[2]; Wv = w[3];
    }

    float *qp, *kp, *vp, *cp;
    cudaGetSymbolAddress((void**)&qp, g_q);
    cudaGetSymbolAddress((void**)&kp, g_k);
    cudaGetSymbolAddress((void**)&vp, g_v);
    cudaGetSymbolAddress((void**)&cp, g_ctx);

    cudaFuncSetAttribute(gemm_tf32,
                         cudaFuncAttributeMaxDynamicSharedMemorySize, GEMM_SMEM);
    cudaFuncSetAttribute(scores_tf32,
                         cudaFuncAttributeMaxDynamicSharedMemorySize, GEMM_SMEM);
    cudaFuncSetAttribute(pv_tf32,
                         cudaFuncAttributeMaxDynamicSharedMemorySize, GEMM_SMEM);

    dim3 gg(HIDDEN / 128, MTOT / 128);   // (16, 32)
    gemm_tf32<<<gg, 256, GEMM_SMEM>>>(x, Wq, qp);
    gemm_tf32<<<gg, 256, GEMM_SMEM>>>(x, Wk, kp);
    gemm_tf32<<<gg, 256, GEMM_SMEM>>>(x, Wv, vp);

    rope2<<<(MTOT * 1024 + 255) / 256, 256>>>();

    scores_tf32<<<dim3(SEQ / 128, SEQ / 128, BH), 256, GEMM_SMEM>>>();
    softmax_rows<<<BH * SEQ, 256>>>();
    pv_tf32<<<dim3(SEQ / 128, BH), 256, GEMM_SMEM>>>();

    gemm_tf32<<<gg, 256, GEMM_SMEM>>>(cp, Wo, (float*)d_out);
}

// round 11
// speedup vs baseline: 1.8280x; 1.5488x over previous
#include <cuda_runtime.h>
#include <cuda_bf16.h>
#include <math.h>
#include <stdint.h>

#define HIDDEN 2048
#define HEADS 16
#define HEAD_DIM 128
#define BATCH 2
#define SEQ 2048
#define MTOT (BATCH * SEQ)     // 4096
#define BH (BATCH * HEADS)     // 32

// ---------------- scratch (device globals; no allocations allowed) ----------
__device__ float g_q[MTOT * HIDDEN];
__device__ float g_k[MTOT * HIDDEN];
__device__ float g_v[MTOT * HIDDEN];
__device__ float g_ctx[MTOT * HIDDEN];
__device__ float g_sc[(size_t)BH * SEQ * SEQ];   // 512 MiB score/prob matrix

// ---------------------------------------------------------------------------
// bf16 split helpers: v = hi + lo, each bf16; packed as bf16x2 words (k-pairs).
// ---------------------------------------------------------------------------
__device__ __forceinline__ void pack_split(float v0, float v1,
                                           uint32_t& hi, uint32_t& lo) {
    __nv_bfloat162 h = __floats2bfloat162_rn(v0, v1);
    float2 hf = __bfloat1622float2(h);
    __nv_bfloat162 l = __floats2bfloat162_rn(v0 - hf.x, v1 - hf.y);
    hi = *reinterpret_cast<uint32_t*>(&h);
    lo = *reinterpret_cast<uint32_t*>(&l);
}

__device__ __forceinline__ void mma_bf16(float* c, const uint32_t* a, const uint32_t* b) {
    asm("mma.sync.aligned.m16n8k16.row.col.f32.bf16.bf16.f32 "
        "{%0,%1,%2,%3}, {%4,%5,%6,%7}, {%8,%9}, {%0,%1,%2,%3};"
        : "+f"(c[0]), "+f"(c[1]), "+f"(c[2]), "+f"(c[3])
        : "r"(a[0]), "r"(a[1]), "r"(a[2]), "r"(a[3]), "r"(b[0]), "r"(b[1]));
}

#define KC 32                    // k floats per chunk = 16 words
#define S2 20                    // words per smem row (16 used + 4 pad)
#define TILE2 (128 * S2)         // words per tile
#define SMEM2 (4 * TILE2 * 4)    // bytes: Ah, Al, Bh, Bl = 40960

// one KC-chunk of 3xBF16 mma on staged hi/lo word tiles
__device__ __forceinline__ void mma_chunk2(
    const uint32_t* Ah, const uint32_t* Al, const uint32_t* Bh, const uint32_t* Bl,
    int wm, int wn, int gid, int tq, float acc[4][4][4]) {
#pragma unroll
    for (int ks = 0; ks < 2; ks++) {
        const int kb = ks * 8;
        uint32_t bh[4][2], bl[4][2];
#pragma unroll
        for (int nt = 0; nt < 4; nt++) {
            int nr = (wn + nt * 8 + gid) * S2 + kb + tq;
            bh[nt][0] = Bh[nr];
            bh[nt][1] = Bh[nr + 4];
            bl[nt][0] = Bl[nr];
            bl[nt][1] = Bl[nr + 4];
        }
        uint32_t af[4][4];
#pragma unroll
        for (int mt = 0; mt < 4; mt++) {
            int r = (wm + mt * 16 + gid) * S2 + kb + tq;
            af[mt][0] = Ah[r];
            af[mt][1] = Ah[r + 8 * S2];
            af[mt][2] = Ah[r + 4];
            af[mt][3] = Ah[r + 8 * S2 + 4];
        }
#pragma unroll
        for (int mt = 0; mt < 4; mt++)
#pragma unroll
            for (int nt = 0; nt < 4; nt++) {
                mma_bf16(acc[mt][nt], af[mt], bh[nt]);   // hi*hi
                mma_bf16(acc[mt][nt], af[mt], bl[nt]);   // hi*lo
            }
#pragma unroll
        for (int mt = 0; mt < 4; mt++) {
            int r = (wm + mt * 16 + gid) * S2 + kb + tq;
            af[mt][0] = Al[r];
            af[mt][1] = Al[r + 8 * S2];
            af[mt][2] = Al[r + 4];
            af[mt][3] = Al[r + 8 * S2 + 4];
        }
#pragma unroll
        for (int mt = 0; mt < 4; mt++)
#pragma unroll
            for (int nt = 0; nt < 4; nt++)
                mma_bf16(acc[mt][nt], af[mt], bh[nt]);   // lo*hi
    }
}

// stage 16 consecutive k-floats (four float4s) as 8 hi + 8 lo words
__device__ __forceinline__ void stage16(const float4* v, uint32_t* Hi, uint32_t* Lo,
                                        int base) {
#pragma unroll
    for (int i = 0; i < 4; i++) {
        uint32_t h0, l0, h1, l1;
        pack_split(v[i].x, v[i].y, h0, l0);
        pack_split(v[i].z, v[i].w, h1, l1);
        Hi[base + 2 * i]     = h0;
        Lo[base + 2 * i]     = l0;
        Hi[base + 2 * i + 1] = h1;
        Lo[base + 2 * i + 1] = l1;
    }
}

// ---------------------------------------------------------------------------
// 3xBF16 NT GEMM: C[M,N] = A[M,K] * W[N,K]^T ; M=4096, N=K=2048.
// Block 128x128, 8 warps (2m x 4n of 64x32 warp tiles), KC=32. R6 structure.
// ---------------------------------------------------------------------------
__global__ __launch_bounds__(256, 2)
void gemm_bf16(const float* __restrict__ A, const float* __restrict__ W,
               float* __restrict__ C) {
    extern __shared__ __align__(16) uint32_t sm[];
    uint32_t* Ah = sm;
    uint32_t* Al = Ah + TILE2;
    uint32_t* Bh = Al + TILE2;
    uint32_t* Bl = Bh + TILE2;

    const int tid = threadIdx.x;
    const int warp = tid >> 5, lane = tid & 31;
    const int gid = lane >> 2, tq = lane & 3;
    const int wm = (warp & 1) * 64;
    const int wn = (warp >> 1) * 32;
    const int m0 = blockIdx.y * 128, n0 = blockIdx.x * 128;
    const int lr = tid >> 1;              // 0..127 load row
    const int lc = (tid & 1) * 16;        // k float base 0/16
    const int wb = (tid & 1) * 8;         // k word base 0/8

    float acc[4][4][4];
#pragma unroll
    for (int mt = 0; mt < 4; mt++)
#pragma unroll
        for (int nt = 0; nt < 4; nt++)
#pragma unroll
            for (int r = 0; r < 4; r++) acc[mt][nt][r] = 0.f;

    const float* Ap = A + (size_t)(m0 + lr) * HIDDEN + lc;
    const float* Wp = W + (size_t)(n0 + lr) * HIDDEN + lc;

    for (int kt = 0; kt < HIDDEN; kt += KC) {
        float4 av[4], wv[4];
#pragma unroll
        for (int i = 0; i < 4; i++) {
            av[i] = *(const float4*)(Ap + kt + 4 * i);
            wv[i] = *(const float4*)(Wp + kt + 4 * i);
        }
        __syncthreads();
        stage16(av, Ah, Al, lr * S2 + wb);
        stage16(wv, Bh, Bl, lr * S2 + wb);
        __syncthreads();
        mma_chunk2(Ah, Al, Bh, Bl, wm, wn, gid, tq, acc);
    }

#pragma unroll
    for (int mt = 0; mt < 4; mt++) {
        int row = m0 + wm + mt * 16 + gid;
#pragma unroll
        for (int nt = 0; nt < 4; nt++) {
            int col = n0 + wn + nt * 8 + 2 * tq;
            *(float2*)&C[(size_t)row * HIDDEN + col] =
                make_float2(acc[mt][nt][0], acc[mt][nt][1]);
            *(float2*)&C[(size_t)(row + 8) * HIDDEN + col] =
                make_float2(acc[mt][nt][2], acc[mt][nt][3]);
        }
    }
}

// ---------------------------------------------------------------------------
// Scores: S = (Q.K^T)*scale, 128x128 lower-triangle blocks. 3xBF16.
// ---------------------------------------------------------------------------
__global__ __launch_bounds__(256, 2)
void scores_bf16() {
    const int k0 = blockIdx.x * 128;
    const int q0 = blockIdx.y * 128;
    if (k0 > q0) return;
    const int bh = blockIdx.z;
    const int b = bh >> 4, h = bh & 15;

    extern __shared__ __align__(16) uint32_t sm[];
    uint32_t* Ah = sm;
    uint32_t* Al = Ah + TILE2;
    uint32_t* Bh = Al + TILE2;
    uint32_t* Bl = Bh + TILE2;

    const int tid = threadIdx.x;
    const int warp = tid >> 5, lane = tid & 31;
    const int gid = lane >> 2, tq = lane & 3;
    const int wm = (warp & 1) * 64;
    const int wn = (warp >> 1) * 32;
    const int lr = tid >> 1;
    const int lc = (tid & 1) * 16;
    const int wb = (tid & 1) * 8;

    const float* Q = g_q + (size_t)b * SEQ * HIDDEN + h * HEAD_DIM;
    const float* K = g_k + (size_t)b * SEQ * HIDDEN + h * HEAD_DIM;
    float* S = g_sc + (size_t)bh * SEQ * SEQ;

    float acc[4][4][4];
#pragma unroll
    for (int mt = 0; mt < 4; mt++)
#pragma unroll
        for (int nt = 0; nt < 4; nt++)
#pragma unroll
            for (int r = 0; r < 4; r++) acc[mt][nt][r] = 0.f;

    const float* Qp = Q + (size_t)(q0 + lr) * HIDDEN + lc;
    const float* Kp = K + (size_t)(k0 + lr) * HIDDEN + lc;

#pragma unroll
    for (int kt = 0; kt < HEAD_DIM; kt += KC) {
        float4 av[4], wv[4];
#pragma unroll
        for (int i = 0; i < 4; i++) {
            av[i] = *(const float4*)(Qp + kt + 4 * i);
            wv[i] = *(const float4*)(Kp + kt + 4 * i);
        }
        __syncthreads();
        stage16(av, Ah, Al, lr * S2 + wb);
        stage16(wv, Bh, Bl, lr * S2 + wb);
        __syncthreads();
        mma_chunk2(Ah, Al, Bh, Bl, wm, wn, gid, tq, acc);
    }

    const float scale = 0.08838834764831845f;  // 1/sqrt(128)
#pragma unroll
    for (int mt = 0; mt < 4; mt++) {
        int row = q0 + wm + mt * 16 + gid;
#pragma unroll
        for (int nt = 0; nt < 4; nt++) {
            int col = k0 + wn + nt * 8 + 2 * tq;
            *(float2*)&S[(size_t)row * SEQ + col] =
                make_float2(acc[mt][nt][0] * scale, acc[mt][nt][1] * scale);
            *(float2*)&S[(size_t)(row + 8) * SEQ + col] =
                make_float2(acc[mt][nt][2] * scale, acc[mt][nt][3] * scale);
        }
    }
}

// ---------------------------------------------------------------------------
// PV: ctx = P * V. P staged k-paired like A; V staged transposed with k-pairs:
// word(d, p) = pack(V[2p][d], V[2p+1][d]). k-loop bounded at q0+128.
// ---------------------------------------------------------------------------
__global__ __launch_bounds__(256, 2)
void pv_bf16() {
    const int q0 = blockIdx.x * 128;
    const int bh = blockIdx.y;
    const int b = bh >> 4, h = bh & 15;

    extern __shared__ __align__(16) uint32_t sm[];
    uint32_t* Ah = sm;
    uint32_t* Al = Ah + TILE2;
    uint32_t* Bh = Al + TILE2;
    uint32_t* Bl = Bh + TILE2;

    const int tid = threadIdx.x;
    const int warp = tid >> 5, lane = tid & 31;
    const int gid = lane >> 2, tq = lane & 3;
    const int wm = (warp & 1) * 64;
    const int wn = (warp >> 1) * 32;
    const int lr = tid >> 1;
    const int lc = (tid & 1) * 16;
    const int wb = (tid & 1) * 8;
    const int vp = tid & 15;              // k-pair index 0..15
    const int vd = (tid >> 4) * 8;        // d base 0..120

    const float* P = g_sc + (size_t)bh * SEQ * SEQ;
    const float* V = g_v + (size_t)b * SEQ * HIDDEN + h * HEAD_DIM;
    float* O = g_ctx + (size_t)b * SEQ * HIDDEN + h * HEAD_DIM;

    float acc[4][4][4];
#pragma unroll
    for (int mt = 0; mt < 4; mt++)
#pragma unroll
        for (int nt = 0; nt < 4; nt++)
#pragma unroll
            for (int r = 0; r < 4; r++) acc[mt][nt][r] = 0.f;

    const int kmax = q0 + 128;
    for (int kt = 0; kt < kmax; kt += KC) {
        float4 pv4[4];
#pragma unroll
        for (int i = 0; i < 4; i++)
            pv4[i] = *(const float4*)&P[(size_t)(q0 + lr) * SEQ + kt + lc + 4 * i];
        // V rows kt+2p and kt+2p+1, d = vd..vd+7
        float4 v0a = *(const float4*)&V[(size_t)(kt + 2 * vp) * HIDDEN + vd];
        float4 v0b = *(const float4*)&V[(size_t)(kt + 2 * vp) * HIDDEN + vd + 4];
        float4 v1a = *(const float4*)&V[(size_t)(kt + 2 * vp + 1) * HIDDEN + vd];
        float4 v1b = *(const float4*)&V[(size_t)(kt + 2 * vp + 1) * HIDDEN + vd + 4];
        __syncthreads();
        stage16(pv4, Ah, Al, lr * S2 + wb);
        {
            float r0[8] = {v0a.x, v0a.y, v0a.z, v0a.w, v0b.x, v0b.y, v0b.z, v0b.w};
            float r1[8] = {v1a.x, v1a.y, v1a.z, v1a.w, v1b.x, v1b.y, v1b.z, v1b.w};
#pragma unroll
            for (int j = 0; j < 8; j++) {
                uint32_t hw, lw;
                pack_split(r0[j], r1[j], hw, lw);   // low half = even k
                Bh[(vd + j) * S2 + vp] = hw;
                Bl[(vd + j) * S2 + vp] = lw;
            }
        }
        __syncthreads();
        mma_chunk2(Ah, Al, Bh, Bl, wm, wn, gid, tq, acc);
    }

#pragma unroll
    for (int mt = 0; mt < 4; mt++) {
        int row = q0 + wm + mt * 16 + gid;
#pragma unroll
        for (int nt = 0; nt < 4; nt++) {
            int col = wn + nt * 8 + 2 * tq;
            *(float2*)&O[(size_t)row * HIDDEN + col] =
                make_float2(acc[mt][nt][0], acc[mt][nt][1]);
            *(float2*)&O[(size_t)(row + 8) * HIDDEN + col] =
                make_float2(acc[mt][nt][2], acc[mt][nt][3]);
        }
    }
}

// ---------------------------------------------------------------------------
// RoPE (unchanged, proven).
// ---------------------------------------------------------------------------
__global__ void rope2() {
    int idx = blockIdx.x * blockDim.x + threadIdx.x;
    if (idx >= MTOT * 1024) return;
    int d = idx & 63;
    int h = (idx >> 6) & 15;
    int row = idx >> 10;
    int s = row & (SEQ - 1);

    double inv = pow(10000.0, -((double)d) / 64.0);
    double ang = (double)s * inv;
    float c = (float)cos(ang);
    float sn = (float)sin(ang);

    size_t i1 = (size_t)row * HIDDEN + h * HEAD_DIM + d;
    float q1 = g_q[i1], q2 = g_q[i1 + 64];
    g_q[i1]      = q1 * c - q2 * sn;
    g_q[i1 + 64] = q2 * c + q1 * sn;
    float k1 = g_k[i1], k2 = g_k[i1 + 64];
    g_k[i1]      = k1 * c - k2 * sn;
    g_k[i1 + 64] = k2 * c + k1 * sn;
}

// ---------------------------------------------------------------------------
// Softmax (unchanged, proven).
// ---------------------------------------------------------------------------
__global__ __launch_bounds__(256)
void softmax_rows() {
    const int row = blockIdx.x;
    const int q = row & (SEQ - 1);
    const int bh = row >> 11;
    float* P = g_sc + (size_t)bh * SEQ * SEQ + (size_t)q * SEQ;
    const int n = q + 1;
    const int tid = threadIdx.x;
    __shared__ float red[256];

    float mx = -1e30f;
    for (int j = tid; j < n; j += 256) mx = fmaxf(mx, P[j]);
    red[tid] = mx;
    __syncthreads();
    for (int s = 128; s > 0; s >>= 1) {
        if (tid < s) red[tid] = fmaxf(red[tid], red[tid + s]);
        __syncthreads();
    }
    float m = red[0];
    __syncthreads();

    float sum = 0.f;
    for (int j = tid; j < n; j += 256) sum += __expf(P[j] - m);
    red[tid] = sum;
    __syncthreads();
    for (int s = 128; s > 0; s >>= 1) {
        if (tid < s) red[tid] += red[tid + s];
        __syncthreads();
    }
    float inv = 1.0f / red[0];

    for (int j = tid; j < n; j += 256) P[j] = __expf(P[j] - m) * inv;
    for (int j = n + tid; j < SEQ; j += 256) P[j] = 0.f;
}

// ---------------------------------------------------------------------------
extern "C" void kernel_launch(void* const* d_in, const int* in_sizes, int n_in,
                              void* d_out, int out_size) {
    int xi = 0;
    for (int i = 0; i < n_in; i++)
        if (in_sizes[i] == MTOT * HIDDEN) { xi = i; break; }

    const float* x;
    const float *Wq, *Wk, *Wv, *Wo;
    if (xi == 0) {
        x  = (const float*)d_in[0];
        Wq = (const float*)d_in[1];
        Wk = (const float*)d_in[2];
        Wv = (const float*)d_in[3];
        Wo = (const float*)d_in[4];
    } else {
        const float* w[4]; int j = 0;
        for (int i = 0; i < n_in; i++)
            if (i != xi) w[j++] = (const float*)d_in[i];
        x = (const float*)d_in[xi];
        Wk = w[0]; Wo = w[1]; Wq = w[2]; Wv = w[3];
    }

    float *qp, *kp, *vp, *cp;
    cudaGetSymbolAddress((void**)&qp, g_q);
    cudaGetSymbolAddress((void**)&kp, g_k);
    cudaGetSymbolAddress((void**)&vp, g_v);
    cudaGetSymbolAddress((void**)&cp, g_ctx);

    cudaFuncSetAttribute(gemm_bf16,
                         cudaFuncAttributeMaxDynamicSharedMemorySize, SMEM2);
    cudaFuncSetAttribute(scores_bf16,
                         cudaFuncAttributeMaxDynamicSharedMemorySize, SMEM2);
    cudaFuncSetAttribute(pv_bf16,
                         cudaFuncAttributeMaxDynamicSharedMemorySize, SMEM2);

    dim3 gg(HIDDEN / 128, MTOT / 128);   // (16, 32)
    gemm_bf16<<<gg, 256, SMEM2>>>(x, Wq, qp);
    gemm_bf16<<<gg, 256, SMEM2>>>(x, Wk, kp);
    gemm_bf16<<<gg, 256, SMEM2>>>(x, Wv, vp);

    rope2<<<(MTOT * 1024 + 255) / 256, 256>>>();

    scores_bf16<<<dim3(SEQ / 128, SEQ / 128, BH), 256, SMEM2>>>();
    softmax_rows<<<BH * SEQ, 256>>>();
    pv_bf16<<<dim3(SEQ / 128, BH), 256, SMEM2>>>();

    gemm_bf16<<<gg, 256, SMEM2>>>(cp, Wo, (float*)d_out);
}